// round 6
// baseline (speedup 1.0000x reference)
#include <cuda_runtime.h>
#include <cuda_bf16.h>
#include <cstdint>

// ---------------- problem dims ----------------
#define B_    32
#define CIN   256
#define H_    56
#define W_    56
#define COUT  256
#define HP    58
#define WP    58
#define HW    (H_*W_)            // 3136
#define M_TOTAL (B_*HW)          // 100352
#define TILE_M 128
#define N_TILES (M_TOTAL/TILE_M) // 784
#define NSTAGE  36               // 9 taps * (256/64 int8 k-chunks)
#define QLOW  (-128.0f)
#define QUP   (127.0f)

// ---------------- scratch (device globals; no allocs) ----------------
__device__ __align__(16) char g_xq[(size_t)B_*HP*WP*CIN];   // padded NHWC int8 x
__device__ __align__(16) char g_wq[NSTAGE*COUT*64];          // [stage][n][64] int8 weights

// ---------------- PTX helpers ----------------
__device__ __forceinline__ uint32_t smem_to_u32(const void* p) {
    uint32_t a;
    asm("{ .reg .u64 t; cvta.to.shared.u64 t, %1; cvt.u32.u64 %0, t; }" : "=r"(a) : "l"(p));
    return a;
}
__device__ __forceinline__ void cp_async16(uint32_t dst, const void* src) {
    asm volatile("cp.async.cg.shared.global [%0], [%1], 16;" :: "r"(dst), "l"(src));
}
#define CP_COMMIT() asm volatile("cp.async.commit_group;" ::: "memory")
#define CP_WAIT(n)  asm volatile("cp.async.wait_group %0;" :: "n"(n) : "memory")

__device__ __forceinline__ void ldsm_x4(uint32_t& r0, uint32_t& r1, uint32_t& r2, uint32_t& r3,
                                        uint32_t addr) {
    asm volatile("ldmatrix.sync.aligned.m8n8.x4.shared.b16 {%0,%1,%2,%3}, [%4];"
                 : "=r"(r0), "=r"(r1), "=r"(r2), "=r"(r3) : "r"(addr));
}
__device__ __forceinline__ void mma_s8(int* d, const uint32_t* a, const uint32_t* b) {
    asm volatile("mma.sync.aligned.m16n8k32.row.col.s32.s8.s8.s32 "
                 "{%0,%1,%2,%3},{%4,%5,%6,%7},{%8,%9},{%0,%1,%2,%3};"
                 : "+r"(d[0]), "+r"(d[1]), "+r"(d[2]), "+r"(d[3])
                 : "r"(a[0]), "r"(a[1]), "r"(a[2]), "r"(a[3]), "r"(b[0]), "r"(b[1]));
}

// ---------------- prep kernels ----------------

// Zero the 1-wide padded border of g_xq. 32 batches * 228 border cells * 256B.
__global__ void xzero_kernel() {
    int i = blockIdx.x * blockDim.x + threadIdx.x;   // < 32*228*16
    if (i >= 32 * 228 * 16) return;
    int cv = i & 15;
    int t  = i >> 4;
    int b  = t / 228;
    int p  = t - b * 228;
    int yp, xp;
    if (p < 58)       { yp = 0;  xp = p; }
    else if (p < 116) { yp = 57; xp = p - 58; }
    else { int q = p - 116; yp = 1 + (q >> 1); xp = (q & 1) ? 57 : 0; }
    *(uint4*)(g_xq + ((size_t)(b * HP + yp) * WP + xp) * CIN + (size_t)cv * 16) =
        make_uint4(0, 0, 0, 0);
}

// Quantize weights -> int8 stage images: g_wq[stage][n][cin&63], stage = (ky*3+kx)*4 + cin/64.
__global__ void wquant_kernel(const float* __restrict__ w, const float* __restrict__ sw) {
    int idx = blockIdx.x * blockDim.x + threadIdx.x;   // < 589824
    int n   = idx / 2304;
    int rem = idx - n * 2304;
    int cin = rem / 9;
    int kk  = rem - cin * 9;                           // ky*3+kx
    float q = rintf(fminf(fmaxf(w[idx] * sw[n], QLOW), QUP));
    g_wq[(size_t)(kk * 4 + (cin >> 6)) * 16384 + (size_t)n * 64 + (cin & 63)] = (char)(int)q;
}

// Quantize x and transpose NCHW -> padded NHWC int8. One block per (b, y) row.
__global__ void xquant_kernel(const float* __restrict__ x, const float* __restrict__ sx) {
    __shared__ char tile[56 * 260];                    // [xx][c], stride 260 (4-aligned)
    int b = blockIdx.x / H_;
    int y = blockIdx.x - b * H_;
    int tid = threadIdx.x;
    float s = sx[0];
    const float* xb = x + ((size_t)(b * CIN) * H_ + y) * W_;  // xb[c*HW + xx]
#pragma unroll 1
    for (int it = 0; it < 56; ++it) {
        int idx = it * 256 + tid;                      // < 14336
        int c  = idx / W_;
        int xx = idx - c * W_;
        float v = xb[(size_t)c * HW + xx];
        float q = rintf(fminf(fmaxf(v * s, QLOW), QUP));
        tile[xx * 260 + c] = (char)(int)q;
    }
    __syncthreads();
    char* dst = g_xq + ((size_t)(b * HP + (y + 1)) * WP + 1) * CIN;
#pragma unroll 1
    for (int it = 0; it < 14; ++it) {                  // 3584 u32 writes
        int idx = it * 256 + tid;
        int xx = idx >> 6;
        int c4 = idx & 63;
        uint32_t v = *(const uint32_t*)&tile[xx * 260 + c4 * 4];
        *(uint32_t*)(dst + (size_t)xx * CIN + c4 * 4) = v;
    }
}

// ---------------- main conv kernel: int8 mma.sync implicit GEMM ----------------
// SMEM: [0,1024) scale f32[256]; [1024,2048) bias; A 2x8KB @2048; B 2x16KB @18432.
#define SM_SCALE 0
#define SM_BIAS  1024
#define SM_A     2048
#define SM_B     18432
#define SMEM_BYTES 51200

__device__ __forceinline__ void issue_stage(int stage, int buf, uint32_t sb,
                                            const char* aRowPtr, int tid) {
    int kk = stage >> 2, kc = stage & 3;
    int dy = kk / 3, dx = kk - dy * 3;
    // A: 128 rows x 64B; thread t -> row t>>1, two 16B segs (c = 2h, 2h+1)
    {
        int h = tid & 1;
        const char* src = aRowPtr + (dy * WP + dx) * CIN + kc * 64;
        uint32_t dstA = sb + SM_A + buf * 8192 + (uint32_t)(tid >> 1) * 64;
        int sw = (tid >> 2) & 3;                        // (row>>1)&3
#pragma unroll
        for (int ci = 0; ci < 2; ++ci) {
            int c = 2 * h + ci;
            cp_async16(dstA + (uint32_t)((c ^ sw) << 4), src + c * 16);
        }
    }
    // B: 256 rows x 64B; thread t -> row t, four 16B segs
    {
        const char* src = g_wq + (size_t)stage * 16384 + (size_t)tid * 64;
        uint32_t dstB = sb + SM_B + buf * 16384 + (uint32_t)tid * 64;
        int sw = (tid >> 1) & 3;
#pragma unroll
        for (int c = 0; c < 4; ++c)
            cp_async16(dstB + (uint32_t)((c ^ sw) << 4), src + c * 16);
    }
}

__global__ __launch_bounds__(256) void conv_mma_kernel(
    const float* __restrict__ bias, const float* __restrict__ sw,
    const float* __restrict__ sx, float* __restrict__ out)
{
    extern __shared__ char smem[];
    uint32_t sb = smem_to_u32(smem);
    int tid  = threadIdx.x;
    int wid  = tid >> 5, lane = tid & 31;
    int warp_m = (wid & 1) * 64;
    int warp_n = (wid >> 1) * 64;

    {   // scale + bias to smem
        float s = sx[0];
        ((float*)(smem + SM_SCALE))[tid] = 1.0f / (s * sw[tid]);
        ((float*)(smem + SM_BIAS))[tid]  = bias[tid];
    }

    int m0 = blockIdx.x * TILE_M;
    // per-thread A gmem row pointer (row = tid>>1 of the M-tile)
    const char* aRowPtr;
    {
        int m = m0 + (tid >> 1);
        int b = m / HW; int rem = m - b * HW;
        int y = rem / W_; int x = rem - y * W_;
        aRowPtr = g_xq + ((size_t)((b * HP + y) * WP + x)) * CIN;
    }

    // per-lane ldmatrix geometry
    int aR   = (lane & 7) + ((lane >> 3) & 1) * 8;      // A row within m16 frag
    int aCH  = lane >> 4;                               // A k-half selector
    uint32_t aRowByte = (uint32_t)(warp_m + aR) * 64;
    int aSw  = (aR >> 1) & 3;
    int bR   = (lane & 7) + ((lane >> 4) << 3);         // B row within n16 group
    int bCH  = (lane >> 3) & 1;
    uint32_t bRowByte = (uint32_t)(warp_n + bR) * 64;
    int bSw  = (bR >> 1) & 3;

    int acc[4][8][4];
#pragma unroll
    for (int f = 0; f < 4; ++f)
#pragma unroll
        for (int g = 0; g < 8; ++g)
#pragma unroll
            for (int r = 0; r < 4; ++r) acc[f][g][r] = 0;

    issue_stage(0, 0, sb, aRowPtr, tid);
    CP_COMMIT();

#pragma unroll 1
    for (int s = 0; s < NSTAGE; ++s) {
        if (s + 1 < NSTAGE) {
            issue_stage(s + 1, (s + 1) & 1, sb, aRowPtr, tid);
            CP_COMMIT();
            CP_WAIT(1);
        } else {
            CP_WAIT(0);
        }
        __syncthreads();

        uint32_t smA = sb + SM_A + (uint32_t)(s & 1) * 8192;
        uint32_t smB = sb + SM_B + (uint32_t)(s & 1) * 16384;
#pragma unroll
        for (int s2 = 0; s2 < 2; ++s2) {
            uint32_t a[4][4];
#pragma unroll
            for (int f = 0; f < 4; ++f)
                ldsm_x4(a[f][0], a[f][1], a[f][2], a[f][3],
                        smA + aRowByte + (uint32_t)f * 1024 +
                        (uint32_t)(((s2 * 2 + aCH) ^ aSw) << 4));
            uint32_t b[8][2];
#pragma unroll
            for (int g = 0; g < 4; ++g)
                ldsm_x4(b[2 * g][0], b[2 * g][1], b[2 * g + 1][0], b[2 * g + 1][1],
                        smB + bRowByte + (uint32_t)g * 1024 +
                        (uint32_t)(((s2 * 2 + bCH) ^ bSw) << 4));
#pragma unroll
            for (int f = 0; f < 4; ++f)
#pragma unroll
                for (int g = 0; g < 8; ++g)
                    mma_s8(acc[f][g], a[f], b[g]);
        }
        __syncthreads();
    }

    // epilogue: acc * (1/(sx*sw[n])) + bias[n], scattered NCHW stores
    const float* scl = (const float*)(smem + SM_SCALE);
    const float* bs  = (const float*)(smem + SM_BIAS);
#pragma unroll
    for (int f = 0; f < 4; ++f) {
        int m1 = m0 + warp_m + f * 16 + (lane >> 2);
        int m2 = m1 + 8;
        int b1 = m1 / HW; int r1 = m1 - b1 * HW; int y1 = r1 / W_; int x1 = r1 - y1 * W_;
        int b2 = m2 / HW; int r2 = m2 - b2 * HW; int y2 = r2 / W_; int x2 = r2 - y2 * W_;
        float* p1 = out + (size_t)b1 * COUT * HW + (size_t)y1 * W_ + x1;
        float* p2 = out + (size_t)b2 * COUT * HW + (size_t)y2 * W_ + x2;
#pragma unroll
        for (int g = 0; g < 8; ++g) {
            int n = warp_n + g * 8 + (lane & 3) * 2;
            float s0 = scl[n], s1 = scl[n + 1];
            float z0 = bs[n],  z1 = bs[n + 1];
            p1[(size_t)n * HW]       = fmaf((float)acc[f][g][0], s0, z0);
            p1[(size_t)(n + 1) * HW] = fmaf((float)acc[f][g][1], s1, z1);
            p2[(size_t)n * HW]       = fmaf((float)acc[f][g][2], s0, z0);
            p2[(size_t)(n + 1) * HW] = fmaf((float)acc[f][g][3], s1, z1);
        }
    }
}

// ---------------- launch ----------------
extern "C" void kernel_launch(void* const* d_in, const int* in_sizes, int n_in,
                              void* d_out, int out_size) {
    const float* x    = (const float*)d_in[0];
    const float* w    = (const float*)d_in[1];
    const float* bias = (const float*)d_in[2];
    const float* sw   = (const float*)d_in[3];
    const float* sx   = (const float*)d_in[4];
    float* out        = (float*)d_out;

    cudaFuncSetAttribute(conv_mma_kernel, cudaFuncAttributeMaxDynamicSharedMemorySize, SMEM_BYTES);

    xzero_kernel<<<456, 256>>>();
    wquant_kernel<<<2304, 256>>>(w, sw);
    xquant_kernel<<<B_ * H_, 256>>>(x, sx);
    conv_mma_kernel<<<N_TILES, 256, SMEM_BYTES>>>(bias, sw, sx, out);
}

// round 7
// speedup vs baseline: 1.0667x; 1.0667x over previous
#include <cuda_runtime.h>
#include <cuda_bf16.h>
#include <cstdint>

// ---------------- problem dims ----------------
#define B_    32
#define CIN   256
#define H_    56
#define W_    56
#define COUT  256
#define HP    58
#define WP    58
#define HW    (H_*W_)            // 3136
#define M_TOTAL (B_*HW)          // 100352
#define TILE_M 128
#define N_TILES (M_TOTAL/TILE_M) // 784
#define NSTAGE  36               // 9 taps * (256/64 int8 k-chunks)
#define THREADS 512
#define QLOW  (-128.0f)
#define QUP   (127.0f)

// ---------------- scratch (device globals; no allocs) ----------------
__device__ __align__(16) char g_xq[(size_t)B_*HP*WP*CIN];   // padded NHWC int8 x
__device__ __align__(16) char g_wq[NSTAGE*COUT*64];          // [stage][n][64] int8 weights

// ---------------- PTX helpers ----------------
__device__ __forceinline__ uint32_t smem_to_u32(const void* p) {
    uint32_t a;
    asm("{ .reg .u64 t; cvta.to.shared.u64 t, %1; cvt.u32.u64 %0, t; }" : "=r"(a) : "l"(p));
    return a;
}
__device__ __forceinline__ void cp_async16(uint32_t dst, const void* src) {
    asm volatile("cp.async.cg.shared.global [%0], [%1], 16;" :: "r"(dst), "l"(src));
}
#define CP_COMMIT() asm volatile("cp.async.commit_group;" ::: "memory")
#define CP_WAIT(n)  asm volatile("cp.async.wait_group %0;" :: "n"(n) : "memory")

__device__ __forceinline__ void ldsm_x4(uint32_t& r0, uint32_t& r1, uint32_t& r2, uint32_t& r3,
                                        uint32_t addr) {
    asm volatile("ldmatrix.sync.aligned.m8n8.x4.shared.b16 {%0,%1,%2,%3}, [%4];"
                 : "=r"(r0), "=r"(r1), "=r"(r2), "=r"(r3) : "r"(addr));
}
__device__ __forceinline__ void mma_s8(int* d, const uint32_t* a, const uint32_t* b) {
    asm volatile("mma.sync.aligned.m16n8k32.row.col.s32.s8.s8.s32 "
                 "{%0,%1,%2,%3},{%4,%5,%6,%7},{%8,%9},{%0,%1,%2,%3};"
                 : "+r"(d[0]), "+r"(d[1]), "+r"(d[2]), "+r"(d[3])
                 : "r"(a[0]), "r"(a[1]), "r"(a[2]), "r"(a[3]), "r"(b[0]), "r"(b[1]));
}

// ---------------- prep kernels ----------------

// Zero the 1-wide padded border of g_xq. 32 batches * 228 border cells * 256B.
__global__ void xzero_kernel() {
    int i = blockIdx.x * blockDim.x + threadIdx.x;   // < 32*228*16
    if (i >= 32 * 228 * 16) return;
    int cv = i & 15;
    int t  = i >> 4;
    int b  = t / 228;
    int p  = t - b * 228;
    int yp, xp;
    if (p < 58)       { yp = 0;  xp = p; }
    else if (p < 116) { yp = 57; xp = p - 58; }
    else { int q = p - 116; yp = 1 + (q >> 1); xp = (q & 1) ? 57 : 0; }
    *(uint4*)(g_xq + ((size_t)(b * HP + yp) * WP + xp) * CIN + (size_t)cv * 16) =
        make_uint4(0, 0, 0, 0);
}

// Quantize weights -> int8 stage images: g_wq[stage][n][cin&63], stage = (ky*3+kx)*4 + cin/64.
__global__ void wquant_kernel(const float* __restrict__ w, const float* __restrict__ sw) {
    int idx = blockIdx.x * blockDim.x + threadIdx.x;   // < 589824
    int n   = idx / 2304;
    int rem = idx - n * 2304;
    int cin = rem / 9;
    int kk  = rem - cin * 9;                           // ky*3+kx
    float q = rintf(fminf(fmaxf(w[idx] * sw[n], QLOW), QUP));
    g_wq[(size_t)(kk * 4 + (cin >> 6)) * 16384 + (size_t)n * 64 + (cin & 63)] = (char)(int)q;
}

// Quantize x and transpose NCHW -> padded NHWC int8. One block per (b, y) row.
__global__ void xquant_kernel(const float* __restrict__ x, const float* __restrict__ sx) {
    __shared__ char tile[56 * 260];                    // [xx][c], stride 260 (4-aligned)
    int b = blockIdx.x / H_;
    int y = blockIdx.x - b * H_;
    int tid = threadIdx.x;
    float s = sx[0];
    const float* xb = x + ((size_t)(b * CIN) * H_ + y) * W_;  // xb[c*HW + xx]
#pragma unroll 1
    for (int it = 0; it < 56; ++it) {
        int idx = it * 256 + tid;                      // < 14336
        int c  = idx / W_;
        int xx = idx - c * W_;
        float v = xb[(size_t)c * HW + xx];
        float q = rintf(fminf(fmaxf(v * s, QLOW), QUP));
        tile[xx * 260 + c] = (char)(int)q;
    }
    __syncthreads();
    char* dst = g_xq + ((size_t)(b * HP + (y + 1)) * WP + 1) * CIN;
#pragma unroll 1
    for (int it = 0; it < 14; ++it) {                  // 3584 u32 writes
        int idx = it * 256 + tid;
        int xx = idx >> 6;
        int c4 = idx & 63;
        uint32_t v = *(const uint32_t*)&tile[xx * 260 + c4 * 4];
        *(uint32_t*)(dst + (size_t)xx * CIN + c4 * 4) = v;
    }
}

// ---------------- main conv kernel: int8 mma.sync implicit GEMM ----------------
// 512 threads, 16 warps, warp tile 32x64, 3-stage cp.async ring, 1 sync/stage.
// SMEM: scale f32[256] @0; bias @1024; A 3x8KB @2048; B 3x16KB @26624.
#define SM_SCALE 0
#define SM_BIAS  1024
#define SM_A     2048
#define SM_B     (2048 + 3*8192)          // 26624
#define SMEM_BYTES (SM_B + 3*16384)       // 75776

__global__ __launch_bounds__(THREADS) void conv_mma_kernel(
    const float* __restrict__ bias, const float* __restrict__ sw,
    const float* __restrict__ sx, float* __restrict__ out)
{
    extern __shared__ char smem[];
    uint32_t sb = smem_to_u32(smem);
    int tid  = threadIdx.x;
    int wid  = tid >> 5, lane = tid & 31;
    int warp_m = (wid & 3) * 32;          // 4 warps over M=128
    int warp_n = (wid >> 2) * 64;         // 4 warps over N=256

    if (tid < 256) {                      // scale + bias to smem
        float s = sx[0];
        ((float*)(smem + SM_SCALE))[tid] = 1.0f / (s * sw[tid]);
        ((float*)(smem + SM_BIAS))[tid]  = bias[tid];
    }

    int m0 = blockIdx.x * TILE_M;

    // ---- per-thread cp.async geometry ----
    // A: 128 rows x 64B; thread t -> row t>>2, seg c = t&3
    const char* aSrc0;
    uint32_t aDst0;
    {
        int row = tid >> 2, c = tid & 3;
        int m = m0 + row;
        int b = m / HW; int rem = m - b * HW;
        int y = rem / W_; int x = rem - y * W_;
        aSrc0 = g_xq + ((size_t)((b * HP + y) * WP + x)) * CIN + c * 16;
        aDst0 = sb + SM_A + (uint32_t)row * 64 + (uint32_t)((c ^ ((row >> 1) & 3)) << 4);
    }
    // B: 256 rows x 64B; thread t -> row t>>1, segs c = 2h, 2h+1
    const char* bSrc0;
    uint32_t bDst0, bDst1;
    {
        int row = tid >> 1, h = tid & 1;
        int sw2 = (row >> 1) & 3;
        bSrc0 = g_wq + (size_t)row * 64 + (size_t)(2 * h) * 16;
        uint32_t base = sb + SM_B + (uint32_t)row * 64;
        bDst0 = base + (uint32_t)(((2 * h)     ^ sw2) << 4);
        bDst1 = base + (uint32_t)(((2 * h + 1) ^ sw2) << 4);
    }

    // ---- per-lane ldmatrix geometry ----
    int aR   = (lane & 7) + ((lane >> 3) & 1) * 8;      // A row within m16 frag
    int aCH  = lane >> 4;                               // A k-half selector
    uint32_t aRowByte = (uint32_t)(warp_m + aR) * 64;
    int aSw  = (aR >> 1) & 3;
    int bR   = (lane & 7) + ((lane >> 4) << 3);         // B row within n16 group
    int bCH  = (lane >> 3) & 1;
    uint32_t bRowByte = (uint32_t)(warp_n + bR) * 64;
    int bSw  = (bR >> 1) & 3;

    int acc[2][8][4];
#pragma unroll
    for (int f = 0; f < 2; ++f)
#pragma unroll
        for (int g = 0; g < 8; ++g)
#pragma unroll
            for (int r = 0; r < 4; ++r) acc[f][g][r] = 0;

    // ---- prologue: stages 0, 1 in flight ----
#pragma unroll
    for (int s = 0; s < 2; ++s) {
        int kk = s >> 2, kc = s & 3;
        int dy = kk / 3, dx = kk - dy * 3;
        cp_async16(aDst0 + (uint32_t)s * 8192, aSrc0 + (dy * WP + dx) * CIN + kc * 64);
        const char* bs2 = bSrc0 + (size_t)s * 16384;
        cp_async16(bDst0 + (uint32_t)s * 16384, bs2);
        cp_async16(bDst1 + (uint32_t)s * 16384, bs2 + 16);
        CP_COMMIT();
    }

    int buf2 = 2;                          // ring slot for stage s+2
#pragma unroll 1
    for (int s = 0; s < NSTAGE; ++s) {
        CP_WAIT(1);                        // stage s resident (FIFO group completion)
        __syncthreads();                   // all CTA writes visible; prior reads of buf2 done

        if (s + 2 < NSTAGE) {              // issue stage s+2 into ring slot buf2
            int s2g = s + 2;
            int kk = s2g >> 2, kc = s2g & 3;
            int dy = kk / 3, dx = kk - dy * 3;
            cp_async16(aDst0 + (uint32_t)buf2 * 8192, aSrc0 + (dy * WP + dx) * CIN + kc * 64);
            const char* bs2 = bSrc0 + (size_t)s2g * 16384;
            cp_async16(bDst0 + (uint32_t)buf2 * 16384, bs2);
            cp_async16(bDst1 + (uint32_t)buf2 * 16384, bs2 + 16);
        }
        CP_COMMIT();                       // always commit (possibly empty) to keep counts uniform

        int bufc = buf2 + 1; if (bufc >= 3) bufc -= 3;   // bufc = s % 3
        uint32_t smA = sb + SM_A + (uint32_t)bufc * 8192;
        uint32_t smB = sb + SM_B + (uint32_t)bufc * 16384;
#pragma unroll
        for (int s2 = 0; s2 < 2; ++s2) {
            uint32_t a[2][4];
#pragma unroll
            for (int f = 0; f < 2; ++f)
                ldsm_x4(a[f][0], a[f][1], a[f][2], a[f][3],
                        smA + aRowByte + (uint32_t)f * 1024 +
                        (uint32_t)(((s2 * 2 + aCH) ^ aSw) << 4));
            uint32_t b[8][2];
#pragma unroll
            for (int g = 0; g < 4; ++g)
                ldsm_x4(b[2 * g][0], b[2 * g][1], b[2 * g + 1][0], b[2 * g + 1][1],
                        smB + bRowByte + (uint32_t)g * 1024 +
                        (uint32_t)(((s2 * 2 + bCH) ^ bSw) << 4));
#pragma unroll
            for (int f = 0; f < 2; ++f)
#pragma unroll
                for (int g = 0; g < 8; ++g)
                    mma_s8(acc[f][g], a[f], b[g]);
        }
        buf2 = bufc;                       // next iteration writes the slot just consumed
    }

    // ---- epilogue: acc * (1/(sx*sw[n])) + bias[n], scattered NCHW stores ----
    const float* scl = (const float*)(smem + SM_SCALE);
    const float* bs  = (const float*)(smem + SM_BIAS);
#pragma unroll
    for (int f = 0; f < 2; ++f) {
        int m1 = m0 + warp_m + f * 16 + (lane >> 2);
        int m2 = m1 + 8;
        int b1 = m1 / HW; int r1 = m1 - b1 * HW; int y1 = r1 / W_; int x1 = r1 - y1 * W_;
        int b2 = m2 / HW; int r2 = m2 - b2 * HW; int y2 = r2 / W_; int x2 = r2 - y2 * W_;
        float* p1 = out + (size_t)b1 * COUT * HW + (size_t)y1 * W_ + x1;
        float* p2 = out + (size_t)b2 * COUT * HW + (size_t)y2 * W_ + x2;
#pragma unroll
        for (int g = 0; g < 8; ++g) {
            int n = warp_n + g * 8 + (lane & 3) * 2;
            float s0 = scl[n], s1 = scl[n + 1];
            float z0 = bs[n],  z1 = bs[n + 1];
            p1[(size_t)n * HW]       = fmaf((float)acc[f][g][0], s0, z0);
            p1[(size_t)(n + 1) * HW] = fmaf((float)acc[f][g][1], s1, z1);
            p2[(size_t)n * HW]       = fmaf((float)acc[f][g][2], s0, z0);
            p2[(size_t)(n + 1) * HW] = fmaf((float)acc[f][g][3], s1, z1);
        }
    }
}

// ---------------- launch ----------------
extern "C" void kernel_launch(void* const* d_in, const int* in_sizes, int n_in,
                              void* d_out, int out_size) {
    const float* x    = (const float*)d_in[0];
    const float* w    = (const float*)d_in[1];
    const float* bias = (const float*)d_in[2];
    const float* sw   = (const float*)d_in[3];
    const float* sx   = (const float*)d_in[4];
    float* out        = (float*)d_out;

    cudaFuncSetAttribute(conv_mma_kernel, cudaFuncAttributeMaxDynamicSharedMemorySize, SMEM_BYTES);

    xzero_kernel<<<456, 256>>>();
    wquant_kernel<<<2304, 256>>>(w, sw);
    xquant_kernel<<<B_ * H_, 256>>>(x, sx);
    conv_mma_kernel<<<N_TILES, THREADS, SMEM_BYTES>>>(bias, sw, sx, out);
}

// round 8
// speedup vs baseline: 1.1692x; 1.0960x over previous
#include <cuda_runtime.h>
#include <cuda_bf16.h>
#include <cstdint>

// ---------------- problem dims ----------------
#define B_    32
#define CIN   256
#define H_    56
#define W_    56
#define COUT  256
#define HP    58
#define WP    58
#define HW    (H_*W_)            // 3136
#define M_TOTAL (B_*HW)          // 100352
#define TILE_M 64
#define N_TILES (M_TOTAL/TILE_M) // 1568
#define NSTAGE  36               // 9 taps * (256/64 int8 k-chunks)
#define THREADS 256
#define QLOW  (-128.0f)
#define QUP   (127.0f)

// ---------------- scratch (device globals; no allocs) ----------------
__device__ __align__(16) char g_xq[(size_t)B_*HP*WP*CIN];   // padded NHWC int8 x
__device__ __align__(16) char g_wq[NSTAGE*COUT*64];          // [stage][n][64] int8 weights

// ---------------- PTX helpers ----------------
__device__ __forceinline__ uint32_t smem_to_u32(const void* p) {
    uint32_t a;
    asm("{ .reg .u64 t; cvta.to.shared.u64 t, %1; cvt.u32.u64 %0, t; }" : "=r"(a) : "l"(p));
    return a;
}
__device__ __forceinline__ void cp_async16(uint32_t dst, const void* src) {
    asm volatile("cp.async.cg.shared.global [%0], [%1], 16;" :: "r"(dst), "l"(src));
}
#define CP_COMMIT() asm volatile("cp.async.commit_group;" ::: "memory")
#define CP_WAIT(n)  asm volatile("cp.async.wait_group %0;" :: "n"(n) : "memory")

__device__ __forceinline__ void ldsm_x4(uint32_t& r0, uint32_t& r1, uint32_t& r2, uint32_t& r3,
                                        uint32_t addr) {
    asm volatile("ldmatrix.sync.aligned.m8n8.x4.shared.b16 {%0,%1,%2,%3}, [%4];"
                 : "=r"(r0), "=r"(r1), "=r"(r2), "=r"(r3) : "r"(addr));
}
__device__ __forceinline__ void mma_s8(int* d, const uint32_t* a, const uint32_t* b) {
    asm volatile("mma.sync.aligned.m16n8k32.row.col.s32.s8.s8.s32 "
                 "{%0,%1,%2,%3},{%4,%5,%6,%7},{%8,%9},{%0,%1,%2,%3};"
                 : "+r"(d[0]), "+r"(d[1]), "+r"(d[2]), "+r"(d[3])
                 : "r"(a[0]), "r"(a[1]), "r"(a[2]), "r"(a[3]), "r"(b[0]), "r"(b[1]));
}

// ---------------- prep kernels ----------------

// Zero the 1-wide padded border of g_xq. 32 batches * 228 border cells * 256B.
__global__ void xzero_kernel() {
    int i = blockIdx.x * blockDim.x + threadIdx.x;   // < 32*228*16
    if (i >= 32 * 228 * 16) return;
    int cv = i & 15;
    int t  = i >> 4;
    int b  = t / 228;
    int p  = t - b * 228;
    int yp, xp;
    if (p < 58)       { yp = 0;  xp = p; }
    else if (p < 116) { yp = 57; xp = p - 58; }
    else { int q = p - 116; yp = 1 + (q >> 1); xp = (q & 1) ? 57 : 0; }
    *(uint4*)(g_xq + ((size_t)(b * HP + yp) * WP + xp) * CIN + (size_t)cv * 16) =
        make_uint4(0, 0, 0, 0);
}

// Quantize weights -> int8 stage images: g_wq[stage][n][cin&63], stage = (ky*3+kx)*4 + cin/64.
__global__ void wquant_kernel(const float* __restrict__ w, const float* __restrict__ sw) {
    int idx = blockIdx.x * blockDim.x + threadIdx.x;   // < 589824
    int n   = idx / 2304;
    int rem = idx - n * 2304;
    int cin = rem / 9;
    int kk  = rem - cin * 9;                           // ky*3+kx
    float q = rintf(fminf(fmaxf(w[idx] * sw[n], QLOW), QUP));
    g_wq[(size_t)(kk * 4 + (cin >> 6)) * 16384 + (size_t)n * 64 + (cin & 63)] = (char)(int)q;
}

// Quantize x and transpose NCHW -> padded NHWC int8. One block per (b, y) row.
__global__ void xquant_kernel(const float* __restrict__ x, const float* __restrict__ sx) {
    __shared__ char tile[56 * 260];                    // [xx][c], stride 260 (4-aligned)
    int b = blockIdx.x / H_;
    int y = blockIdx.x - b * H_;
    int tid = threadIdx.x;
    float s = sx[0];
    const float* xb = x + ((size_t)(b * CIN) * H_ + y) * W_;  // xb[c*HW + xx]
#pragma unroll 1
    for (int it = 0; it < 56; ++it) {
        int idx = it * 256 + tid;                      // < 14336
        int c  = idx / W_;
        int xx = idx - c * W_;
        float v = xb[(size_t)c * HW + xx];
        float q = rintf(fminf(fmaxf(v * s, QLOW), QUP));
        tile[xx * 260 + c] = (char)(int)q;
    }
    __syncthreads();
    char* dst = g_xq + ((size_t)(b * HP + (y + 1)) * WP + 1) * CIN;
#pragma unroll 1
    for (int it = 0; it < 14; ++it) {                  // 3584 u32 writes
        int idx = it * 256 + tid;
        int xx = idx >> 6;
        int c4 = idx & 63;
        uint32_t v = *(const uint32_t*)&tile[xx * 260 + c4 * 4];
        *(uint32_t*)(dst + (size_t)xx * CIN + c4 * 4) = v;
    }
}

// ---------------- main conv kernel: int8 mma.sync implicit GEMM ----------------
// 256 threads, 8 warps, warp tile 32x64, TILE_M=64, 4-stage cp.async ring,
// 2 CTAs/SM co-resident. SMEM: scale @0; bias @1024; A 4x4KB @2048; B 4x16KB @18432.
#define SM_SCALE 0
#define SM_BIAS  1024
#define SM_A     2048
#define SM_B     (2048 + 4*4096)          // 18432
#define SMEM_BYTES (SM_B + 4*16384)       // 83968

__global__ __launch_bounds__(THREADS, 2) void conv_mma_kernel(
    const float* __restrict__ bias, const float* __restrict__ sw,
    const float* __restrict__ sx, float* __restrict__ out)
{
    extern __shared__ char smem[];
    uint32_t sb = smem_to_u32(smem);
    int tid  = threadIdx.x;
    int wid  = tid >> 5, lane = tid & 31;
    int warp_m = (wid & 1) * 32;          // 2 warps over M=64
    int warp_n = (wid >> 1) * 64;         // 4 warps over N=256

    {                                     // scale + bias to smem
        float s = sx[0];
        ((float*)(smem + SM_SCALE))[tid] = 1.0f / (s * sw[tid]);
        ((float*)(smem + SM_BIAS))[tid]  = bias[tid];
    }

    int m0 = blockIdx.x * TILE_M;

    // ---- per-thread cp.async geometry ----
    // A: 64 rows x 64B; thread t -> row t>>2, seg c = t&3
    const char* aSrc0;
    uint32_t aDst0;
    {
        int row = tid >> 2, c = tid & 3;
        int m = m0 + row;
        int b = m / HW; int rem = m - b * HW;
        int y = rem / W_; int x = rem - y * W_;
        aSrc0 = g_xq + ((size_t)((b * HP + y) * WP + x)) * CIN + c * 16;
        aDst0 = sb + SM_A + (uint32_t)row * 64 + (uint32_t)((c ^ ((row >> 1) & 3)) << 4);
    }
    // B: 256 rows x 64B; thread t -> row t, segs c = 0..3
    const char* bSrc0 = g_wq + (size_t)tid * 64;
    uint32_t bDst[4];
    {
        int sw2 = (tid >> 1) & 3;
        uint32_t base = sb + SM_B + (uint32_t)tid * 64;
#pragma unroll
        for (int c = 0; c < 4; ++c) bDst[c] = base + (uint32_t)((c ^ sw2) << 4);
    }

    // ---- per-lane ldmatrix geometry ----
    int aR   = (lane & 7) + ((lane >> 3) & 1) * 8;      // A row within m16 frag
    int aCH  = lane >> 4;                               // A k-half selector
    uint32_t aRowByte = (uint32_t)(warp_m + aR) * 64;
    int aSw  = (aR >> 1) & 3;
    int bR   = (lane & 7) + ((lane >> 4) << 3);         // B row within n16 group
    int bCH  = (lane >> 3) & 1;
    uint32_t bRowByte = (uint32_t)(warp_n + bR) * 64;
    int bSw  = (bR >> 1) & 3;

    int acc[2][8][4];
#pragma unroll
    for (int f = 0; f < 2; ++f)
#pragma unroll
        for (int g = 0; g < 8; ++g)
#pragma unroll
            for (int r = 0; r < 4; ++r) acc[f][g][r] = 0;

    // ---- prologue: stages 0..2 in flight ----
#pragma unroll
    for (int s = 0; s < 3; ++s) {
        int kk = s >> 2, kc = s & 3;
        int dy = kk / 3, dx = kk - dy * 3;
        cp_async16(aDst0 + (uint32_t)s * 4096, aSrc0 + (dy * WP + dx) * CIN + kc * 64);
        const char* bs2 = bSrc0 + (size_t)s * 16384;
#pragma unroll
        for (int c = 0; c < 4; ++c)
            cp_async16(bDst[c] + (uint32_t)s * 16384, bs2 + c * 16);
        CP_COMMIT();
    }

#pragma unroll 1
    for (int s = 0; s < NSTAGE; ++s) {
        CP_WAIT(2);                        // stage s resident (FIFO group completion)
        __syncthreads();                   // writes visible; prior reads of slot (s+3)&3 done

        if (s + 3 < NSTAGE) {              // issue stage s+3 into ring slot (s+3)&3
            int sg = s + 3;
            int slot = sg & 3;
            int kk = sg >> 2, kc = sg & 3;
            int dy = kk / 3, dx = kk - dy * 3;
            cp_async16(aDst0 + (uint32_t)slot * 4096, aSrc0 + (dy * WP + dx) * CIN + kc * 64);
            const char* bs2 = bSrc0 + (size_t)sg * 16384;
#pragma unroll
            for (int c = 0; c < 4; ++c)
                cp_async16(bDst[c] + (uint32_t)slot * 16384, bs2 + c * 16);
        }
        CP_COMMIT();                       // always commit (possibly empty): uniform group math

        int bufc = s & 3;
        uint32_t smA = sb + SM_A + (uint32_t)bufc * 4096;
        uint32_t smB = sb + SM_B + (uint32_t)bufc * 16384;
#pragma unroll
        for (int s2 = 0; s2 < 2; ++s2) {
            uint32_t a[2][4];
#pragma unroll
            for (int f = 0; f < 2; ++f)
                ldsm_x4(a[f][0], a[f][1], a[f][2], a[f][3],
                        smA + aRowByte + (uint32_t)f * 1024 +
                        (uint32_t)(((s2 * 2 + aCH) ^ aSw) << 4));
            uint32_t b[8][2];
#pragma unroll
            for (int g = 0; g < 4; ++g)
                ldsm_x4(b[2 * g][0], b[2 * g][1], b[2 * g + 1][0], b[2 * g + 1][1],
                        smB + bRowByte + (uint32_t)g * 1024 +
                        (uint32_t)(((s2 * 2 + bCH) ^ bSw) << 4));
#pragma unroll
            for (int f = 0; f < 2; ++f)
#pragma unroll
                for (int g = 0; g < 8; ++g)
                    mma_s8(acc[f][g], a[f], b[g]);
        }
    }

    // ---- epilogue: acc * (1/(sx*sw[n])) + bias[n], scattered NCHW stores ----
    const float* scl = (const float*)(smem + SM_SCALE);
    const float* bs  = (const float*)(smem + SM_BIAS);
#pragma unroll
    for (int f = 0; f < 2; ++f) {
        int m1 = m0 + warp_m + f * 16 + (lane >> 2);
        int m2 = m1 + 8;
        int b1 = m1 / HW; int r1 = m1 - b1 * HW; int y1 = r1 / W_; int x1 = r1 - y1 * W_;
        int b2 = m2 / HW; int r2 = m2 - b2 * HW; int y2 = r2 / W_; int x2 = r2 - y2 * W_;
        float* p1 = out + (size_t)b1 * COUT * HW + (size_t)y1 * W_ + x1;
        float* p2 = out + (size_t)b2 * COUT * HW + (size_t)y2 * W_ + x2;
#pragma unroll
        for (int g = 0; g < 8; ++g) {
            int n = warp_n + g * 8 + (lane & 3) * 2;
            float s0 = scl[n], s1 = scl[n + 1];
            float z0 = bs[n],  z1 = bs[n + 1];
            p1[(size_t)n * HW]       = fmaf((float)acc[f][g][0], s0, z0);
            p1[(size_t)(n + 1) * HW] = fmaf((float)acc[f][g][1], s1, z1);
            p2[(size_t)n * HW]       = fmaf((float)acc[f][g][2], s0, z0);
            p2[(size_t)(n + 1) * HW] = fmaf((float)acc[f][g][3], s1, z1);
        }
    }
}

// ---------------- launch ----------------
extern "C" void kernel_launch(void* const* d_in, const int* in_sizes, int n_in,
                              void* d_out, int out_size) {
    const float* x    = (const float*)d_in[0];
    const float* w    = (const float*)d_in[1];
    const float* bias = (const float*)d_in[2];
    const float* sw   = (const float*)d_in[3];
    const float* sx   = (const float*)d_in[4];
    float* out        = (float*)d_out;

    cudaFuncSetAttribute(conv_mma_kernel, cudaFuncAttributeMaxDynamicSharedMemorySize, SMEM_BYTES);

    xzero_kernel<<<456, 256>>>();
    wquant_kernel<<<2304, 256>>>(w, sw);
    xquant_kernel<<<B_ * H_, 256>>>(x, sx);
    conv_mma_kernel<<<N_TILES, THREADS, SMEM_BYTES>>>(bias, sw, sx, out);
}